// round 12
// baseline (speedup 1.0000x reference)
#include <cuda_runtime.h>
#include <cuda_bf16.h>

#define USER_NUM 100000
#define ITEM_NUM 50000
#define N_NODES  150000
#define EMB      64
#define LAYERS   3
#define NNZ      2400000

#define TILE 64
#define SROW 68          // padded smem row stride (floats)
#define NB_SCAN 147      // ceil(150000/1024)

// ---------------- device scratch (static globals: allocation-free) ----------
__device__ float g_egoA[N_NODES * EMB];
__device__ float g_egoB[N_NODES * EMB];
__device__ float g_acc [N_NODES * EMB];
__device__ int   g_rowptr[N_NODES + 1];
__device__ int   g_cursor[N_NODES];
__device__ int   g_counts[N_NODES];            // zero-init; re-zeroed each run
__device__ unsigned long long g_state[160];    // lookback state; re-zeroed each run

__device__ int2  g_edges[NNZ];           // .x = col, .y = bits(val)

// ---------------- f32x2 helpers ---------------------------------------------
__device__ __forceinline__ unsigned long long f2fma(unsigned long long a,
                                                    unsigned long long b,
                                                    unsigned long long c) {
    unsigned long long d;
    asm("fma.rn.f32x2 %0, %1, %2, %3;" : "=l"(d) : "l"(a), "l"(b), "l"(c));
    return d;
}
__device__ __forceinline__ unsigned long long f2dup(float x) {
    unsigned long long d;
    asm("mov.b64 %0, {%1, %1};" : "=l"(d) : "r"(__float_as_uint(x)));
    return d;
}
__device__ __forceinline__ void f2unpack(unsigned long long v, float& lo, float& hi) {
    unsigned int a, b;
    asm("mov.b64 {%0, %1}, %2;" : "=r"(a), "=r"(b) : "l"(v));
    lo = __uint_as_float(a); hi = __uint_as_float(b);
}

// -------- launch 1: embedding init + row histogram (counts pre-zeroed) ------
__global__ void k_init_hist(const float* __restrict__ u, const float* __restrict__ it,
                            const int* __restrict__ rows) {
    int i = blockIdx.x * blockDim.x + threadIdx.x;
    if (i < USER_NUM * EMB) {
        float v = u[i];
        g_egoA[i] = v; g_acc[i] = v;
    } else if (i < N_NODES * EMB) {
        float v = it[i - USER_NUM * EMB];
        g_egoA[i] = v; g_acc[i] = v;
    }
    if (i < NNZ) atomicAdd(&g_counts[rows[i]], 1);
}

// -------- launch 2: single-kernel decoupled-lookback exclusive scan ---------
__global__ void __launch_bounds__(1024) k_scan_lookback() {
    __shared__ int sm[1024];
    __shared__ unsigned int s_prefix;
    int idx = blockIdx.x * 1024 + threadIdx.x;
    int v = (idx < N_NODES) ? g_counts[idx] : 0;
    sm[threadIdx.x] = v;
    __syncthreads();
    #pragma unroll
    for (int off = 1; off < 1024; off <<= 1) {
        int t = (threadIdx.x >= off) ? sm[threadIdx.x - off] : 0;
        __syncthreads();
        sm[threadIdx.x] += t;
        __syncthreads();
    }
    if (threadIdx.x == 0) {
        unsigned int agg = (unsigned int)sm[1023];
        atomicExch(&g_state[blockIdx.x], (1ull << 32) | (unsigned long long)agg);
        unsigned int prefix = 0;
        int j = (int)blockIdx.x - 1;
        while (j >= 0) {
            unsigned long long st = atomicAdd(&g_state[j], 0ull);
            unsigned int flag = (unsigned int)(st >> 32);
            if (flag == 2u) { prefix += (unsigned int)st; break; }
            if (flag == 1u) { prefix += (unsigned int)st; j--; }
        }
        atomicExch(&g_state[blockIdx.x],
                   (2ull << 32) | (unsigned long long)(prefix + agg));
        s_prefix = prefix;
    }
    __syncthreads();
    if (idx < N_NODES) {
        int r = (sm[threadIdx.x] - v) + (int)s_prefix;   // exclusive + carry
        g_rowptr[idx] = r;
        g_cursor[idx] = r;
    }
    if (blockIdx.x == 0 && threadIdx.x == 0) g_rowptr[N_NODES] = NNZ;
}

// -------- launch 3: scatter edges into CSR; reset counts/state for next run -
__global__ void k_scatter(const int* __restrict__ rows, const int* __restrict__ cols,
                          const float* __restrict__ vals) {
    int i = blockIdx.x * blockDim.x + threadIdx.x;
    if (i < NNZ) {
        int r = rows[i];
        int p = atomicAdd(&g_cursor[r], 1);
        g_edges[p] = make_int2(cols[i], __float_as_int(vals[i]));
    }
    if (i < N_NODES) g_counts[i] = 0;
    if (i < 160)     g_state[i]  = 0ull;
}

// ------------- fused layer: tile of 64 rows per block -----------------------
//   phase 1: gather g = (A@src)[row]; stage S = src+g, Z = src*g in smem
//   phase 2: O = S@w1 + Z@w2; thread = 4 rows x 4 cols (f32x2, u64 weights)
__global__ void __launch_bounds__(256) k_fused(const float* __restrict__ w1,
                                               const float* __restrict__ w2,
                                               float* __restrict__ dout,
                                               int parity, int final_layer) {
    __shared__ __align__(16) float sS[TILE * SROW];
    __shared__ __align__(16) float sZ[TILE * SROW];

    const float* __restrict__ src = parity ? g_egoB : g_egoA;
    float* __restrict__ dst       = parity ? g_egoA : g_egoB;

    int tid  = threadIdx.x;
    int lane = tid & 31;
    int warp = tid >> 5;
    const int ntiles = (N_NODES + TILE - 1) / TILE;

    for (int t = blockIdx.x; t < ntiles; t += gridDim.x) {
        int row0 = t * TILE;

        // ---- phase 1: gather (8 warps x 8 rows) ----
        #pragma unroll
        for (int rr = 0; rr < 8; rr++) {
            int lr  = warp * 8 + rr;
            int row = row0 + lr;
            if (row < N_NODES) {
                int s = g_rowptr[row], e = g_rowptr[row + 1];
                float g0 = 0.f, g1 = 0.f, h0 = 0.f, h1 = 0.f;
                int i = s;
                for (; i + 1 < e; i += 2) {
                    int2 e0 = g_edges[i];
                    int2 e1 = g_edges[i + 1];
                    float v0 = __int_as_float(e0.y);
                    float v1 = __int_as_float(e1.y);
                    const float* p0 = src + e0.x * 64;
                    const float* p1 = src + e1.x * 64;
                    g0 += v0 * p0[lane]; g1 += v0 * p0[lane + 32];
                    h0 += v1 * p1[lane]; h1 += v1 * p1[lane + 32];
                }
                if (i < e) {
                    int2 e0 = g_edges[i];
                    float v0 = __int_as_float(e0.y);
                    const float* p0 = src + e0.x * 64;
                    g0 += v0 * p0[lane]; g1 += v0 * p0[lane + 32];
                }
                g0 += h0; g1 += h1;
                float e0v = src[row * 64 + lane];
                float e1v = src[row * 64 + lane + 32];
                sS[lr * SROW + lane]      = e0v + g0;
                sS[lr * SROW + lane + 32] = e1v + g1;
                sZ[lr * SROW + lane]      = e0v * g0;
                sZ[lr * SROW + lane + 32] = e1v * g1;
            } else {
                sS[lr * SROW + lane] = 0.f; sS[lr * SROW + lane + 32] = 0.f;
                sZ[lr * SROW + lane] = 0.f; sZ[lr * SROW + lane + 32] = 0.f;
            }
        }
        __syncthreads();

        // ---- phase 2: GEMM, thread = 4 rows x 4 cols ----
        int rg = tid >> 4;          // 0..15 -> rows 4rg..4rg+3
        int cg = tid & 15;          // cols 4cg..4cg+3
        int rbase = 4 * rg;
        unsigned long long acc[4][2];
        #pragma unroll
        for (int r = 0; r < 4; r++) { acc[r][0] = 0ull; acc[r][1] = 0ull; }

        #pragma unroll
        for (int k = 0; k < 64; k += 4) {
            float4 sv[4], zv[4];
            #pragma unroll
            for (int r = 0; r < 4; r++) {
                sv[r] = *(const float4*)&sS[(rbase + r) * SROW + k];
                zv[r] = *(const float4*)&sZ[(rbase + r) * SROW + k];
            }
            #pragma unroll
            for (int kk = 0; kk < 4; kk++) {
                ulonglong2 aw = __ldg((const ulonglong2*)&w1[(k + kk) * 64 + 4 * cg]);
                ulonglong2 bw = __ldg((const ulonglong2*)&w2[(k + kk) * 64 + 4 * cg]);
                #pragma unroll
                for (int r = 0; r < 4; r++) {
                    float sf = (kk == 0) ? sv[r].x : (kk == 1) ? sv[r].y
                              : (kk == 2) ? sv[r].z : sv[r].w;
                    float zf = (kk == 0) ? zv[r].x : (kk == 1) ? zv[r].y
                              : (kk == 2) ? zv[r].z : zv[r].w;
                    unsigned long long sd = f2dup(sf);
                    unsigned long long zd = f2dup(zf);
                    acc[r][0] = f2fma(sd, aw.x, acc[r][0]);
                    acc[r][0] = f2fma(zd, bw.x, acc[r][0]);
                    acc[r][1] = f2fma(sd, aw.y, acc[r][1]);
                    acc[r][1] = f2fma(zd, bw.y, acc[r][1]);
                }
            }
        }

        // ---- epilogue ----
        #pragma unroll
        for (int r = 0; r < 4; r++) {
            int row = row0 + rbase + r;
            if (row < N_NODES) {
                float o0, o1, o2, o3;
                f2unpack(acc[r][0], o0, o1);
                f2unpack(acc[r][1], o2, o3);
                o0 = (o0 > 0.f) ? o0 : 0.01f * o0;
                o1 = (o1 > 0.f) ? o1 : 0.01f * o1;
                o2 = (o2 > 0.f) ? o2 : 0.01f * o2;
                o3 = (o3 > 0.f) ? o3 : 0.01f * o3;
                int base = row * 64 + 4 * cg;
                if (final_layer) {
                    float4 ac = *(const float4*)&g_acc[base];
                    float4 res;
                    res.x = (ac.x + o0) * 0.25f;
                    res.y = (ac.y + o1) * 0.25f;
                    res.z = (ac.z + o2) * 0.25f;
                    res.w = (ac.w + o3) * 0.25f;
                    *(float4*)&dout[base] = res;
                } else {
                    *(float4*)&dst[base] = make_float4(o0, o1, o2, o3);
                    float4 ac = *(const float4*)&g_acc[base];
                    ac.x += o0; ac.y += o1; ac.z += o2; ac.w += o3;
                    *(float4*)&g_acc[base] = ac;
                }
            }
        }
        __syncthreads();   // protect sS/sZ before next tile
    }
}

// ---------------- launch -----------------------------------------------------
extern "C" void kernel_launch(void* const* d_in, const int* in_sizes, int n_in,
                              void* d_out, int out_size) {
    const float* user_emb = (const float*)d_in[0];
    const float* item_emb = (const float*)d_in[1];
    const float* w1       = (const float*)d_in[2];   // [3,64,64]
    const float* w2       = (const float*)d_in[3];   // [3,64,64]
    const float* adj_vals = (const float*)d_in[4];
    const int*   adj_rows = (const int*)d_in[5];
    const int*   adj_cols = (const int*)d_in[6];
    float* dout = (float*)d_out;

    // exactly 3 launches before the first k_fused so ncu (-s 5) profiles k_fused.
    k_init_hist<<<(N_NODES * EMB + 255) / 256, 256>>>(user_emb, item_emb, adj_rows);
    k_scan_lookback<<<NB_SCAN, 1024>>>();
    k_scatter<<<(NNZ + 255) / 256, 256>>>(adj_rows, adj_cols, adj_vals);

    const int FUSED_BLOCKS = 1184;   // grid-stride over 2344 tiles

    for (int k = 0; k < LAYERS; k++) {
        k_fused<<<FUSED_BLOCKS, 256>>>(w1 + k * EMB * EMB, w2 + k * EMB * EMB,
                                       dout, k & 1, k == LAYERS - 1);
    }
    (void)in_sizes; (void)n_in; (void)out_size;
}

// round 13
// speedup vs baseline: 1.0972x; 1.0972x over previous
#include <cuda_runtime.h>
#include <cuda_bf16.h>

#define USER_NUM 100000
#define ITEM_NUM 50000
#define N_NODES  150000
#define EMB      64
#define LAYERS   3
#define NNZ      2400000

#define TILE 32
#define NB_SCAN 147      // ceil(150000/1024)

// ---------------- device scratch (static globals: allocation-free) ----------
__device__ float g_egoA[N_NODES * EMB];
__device__ float g_egoB[N_NODES * EMB];
__device__ float g_aggE[N_NODES * EMB];
__device__ float g_acc [N_NODES * EMB];
__device__ int   g_rowptr[N_NODES + 1];
__device__ int   g_cursor[N_NODES];
__device__ int   g_counts[N_NODES];            // zero-init; re-zeroed each run
__device__ unsigned long long g_state[160];    // lookback state; re-zeroed each run

__device__ int2  g_edges[NNZ];           // .x = col, .y = bits(val)

// ---------------- f32x2 helpers ---------------------------------------------
__device__ __forceinline__ unsigned long long f2fma(unsigned long long a,
                                                    unsigned long long b,
                                                    unsigned long long c) {
    unsigned long long d;
    asm("fma.rn.f32x2 %0, %1, %2, %3;" : "=l"(d) : "l"(a), "l"(b), "l"(c));
    return d;
}
__device__ __forceinline__ unsigned long long f2dup(float x) {
    unsigned long long d;
    asm("mov.b64 %0, {%1, %1};" : "=l"(d) : "r"(__float_as_uint(x)));
    return d;
}
__device__ __forceinline__ void f2unpack(unsigned long long v, float& lo, float& hi) {
    unsigned int a, b;
    asm("mov.b64 {%0, %1}, %2;" : "=r"(a), "=r"(b) : "l"(v));
    lo = __uint_as_float(a); hi = __uint_as_float(b);
}

// -------- launch 1: embedding init + row histogram (counts pre-zeroed) ------
__global__ void k_init_hist(const float* __restrict__ u, const float* __restrict__ it,
                            const int* __restrict__ rows) {
    int i = blockIdx.x * blockDim.x + threadIdx.x;
    if (i < USER_NUM * EMB) {
        float v = u[i];
        g_egoA[i] = v; g_acc[i] = v;
    } else if (i < N_NODES * EMB) {
        float v = it[i - USER_NUM * EMB];
        g_egoA[i] = v; g_acc[i] = v;
    }
    if (i < NNZ) atomicAdd(&g_counts[rows[i]], 1);
}

// -------- launch 2: single-kernel decoupled-lookback exclusive scan ---------
__global__ void __launch_bounds__(1024) k_scan_lookback() {
    __shared__ int sm[1024];
    __shared__ unsigned int s_prefix;
    int idx = blockIdx.x * 1024 + threadIdx.x;
    int v = (idx < N_NODES) ? g_counts[idx] : 0;
    sm[threadIdx.x] = v;
    __syncthreads();
    #pragma unroll
    for (int off = 1; off < 1024; off <<= 1) {
        int t = (threadIdx.x >= off) ? sm[threadIdx.x - off] : 0;
        __syncthreads();
        sm[threadIdx.x] += t;
        __syncthreads();
    }
    if (threadIdx.x == 0) {
        unsigned int agg = (unsigned int)sm[1023];
        atomicExch(&g_state[blockIdx.x], (1ull << 32) | (unsigned long long)agg);
        unsigned int prefix = 0;
        int j = (int)blockIdx.x - 1;
        while (j >= 0) {
            unsigned long long st = atomicAdd(&g_state[j], 0ull);
            unsigned int flag = (unsigned int)(st >> 32);
            if (flag == 2u) { prefix += (unsigned int)st; break; }
            if (flag == 1u) { prefix += (unsigned int)st; j--; }
        }
        atomicExch(&g_state[blockIdx.x],
                   (2ull << 32) | (unsigned long long)(prefix + agg));
        s_prefix = prefix;
    }
    __syncthreads();
    if (idx < N_NODES) {
        int r = (sm[threadIdx.x] - v) + (int)s_prefix;   // exclusive + carry
        g_rowptr[idx] = r;
        g_cursor[idx] = r;
    }
    if (blockIdx.x == 0 && threadIdx.x == 0) g_rowptr[N_NODES] = NNZ;
}

// -------- launch 3: scatter edges into CSR; reset counts/state for next run -
__global__ void k_scatter(const int* __restrict__ rows, const int* __restrict__ cols,
                          const float* __restrict__ vals) {
    int i = blockIdx.x * blockDim.x + threadIdx.x;
    if (i < NNZ) {
        int r = rows[i];
        int p = atomicAdd(&g_cursor[r], 1);
        g_edges[p] = make_int2(cols[i], __float_as_int(vals[i]));
    }
    if (i < N_NODES) g_counts[i] = 0;
    if (i < 160)     g_state[i]  = 0ull;
}

// ------------- SpMM: aggE[row] = sum_e v * src[col]  (warp per row) --------
//   lean register footprint -> max occupancy for latency hiding
__global__ void __launch_bounds__(256) k_spmm(int parity) {
    const float* __restrict__ src = parity ? g_egoB : g_egoA;
    int gw = (blockIdx.x * blockDim.x + threadIdx.x) >> 5;
    if (gw >= N_NODES) return;
    int lane = threadIdx.x & 31;
    int s = g_rowptr[gw], e = g_rowptr[gw + 1];
    float g0 = 0.f, g1 = 0.f, h0 = 0.f, h1 = 0.f;
    int i = s;
    for (; i + 1 < e; i += 2) {
        int2 e0 = g_edges[i];
        int2 e1 = g_edges[i + 1];
        float v0 = __int_as_float(e0.y);
        float v1 = __int_as_float(e1.y);
        const float* p0 = src + e0.x * 64;
        const float* p1 = src + e1.x * 64;
        g0 += v0 * p0[lane]; g1 += v0 * p0[lane + 32];
        h0 += v1 * p1[lane]; h1 += v1 * p1[lane + 32];
    }
    if (i < e) {
        int2 e0 = g_edges[i];
        float v0 = __int_as_float(e0.y);
        const float* p0 = src + e0.x * 64;
        g0 += v0 * p0[lane]; g1 += v0 * p0[lane + 32];
    }
    g_aggE[gw * 64 + lane]      = g0 + h0;
    g_aggE[gw * 64 + lane + 32] = g1 + h1;
}

// ------------- layer: tile of 32 rows; S/Z built from ego+aggE --------------
//   O = S@w1 + Z@w2 (2 rows x 4 cols per thread, f32x2, __ldg weights)
__global__ void __launch_bounds__(256) k_layer(const float* __restrict__ w1,
                                               const float* __restrict__ w2,
                                               float* __restrict__ dout,
                                               int parity, int final_layer) {
    __shared__ __align__(16) float sS[TILE * 64];
    __shared__ __align__(16) float sZ[TILE * 64];

    const float* __restrict__ src = parity ? g_egoB : g_egoA;
    float* __restrict__ dst       = parity ? g_egoA : g_egoB;

    int tid  = threadIdx.x;
    int row0 = blockIdx.x * TILE;
    int gbase = row0 * 64;

    // stage S = e + g, Z = e * g (linear coalesced float4 copies)
    #pragma unroll
    for (int c = 0; c < 2; c++) {
        int j = (tid + c * 256) * 4;              // 0..2047 floats
        if (gbase + j < N_NODES * 64) {
            float4 ev = *(const float4*)&src[gbase + j];
            float4 gv = *(const float4*)&g_aggE[gbase + j];
            float4 s4, z4;
            s4.x = ev.x + gv.x; z4.x = ev.x * gv.x;
            s4.y = ev.y + gv.y; z4.y = ev.y * gv.y;
            s4.z = ev.z + gv.z; z4.z = ev.z * gv.z;
            s4.w = ev.w + gv.w; z4.w = ev.w * gv.w;
            *(float4*)&sS[j] = s4;
            *(float4*)&sZ[j] = z4;
        } else {
            *(float4*)&sS[j] = make_float4(0.f, 0.f, 0.f, 0.f);
            *(float4*)&sZ[j] = make_float4(0.f, 0.f, 0.f, 0.f);
        }
    }
    __syncthreads();

    // GEMM: thread = 2 rows x 4 cols
    int rg = tid >> 4;          // 0..15 -> rows 2rg, 2rg+1
    int cg = tid & 15;          // cols 4cg..4cg+3
    int r0 = 2 * rg, r1 = r0 + 1;
    unsigned long long acc00 = 0ull, acc01 = 0ull, acc10 = 0ull, acc11 = 0ull;

    #pragma unroll
    for (int k = 0; k < 64; k += 4) {
        float4 sv0 = *(const float4*)&sS[r0 * 64 + k];
        float4 sv1 = *(const float4*)&sS[r1 * 64 + k];
        float4 zv0 = *(const float4*)&sZ[r0 * 64 + k];
        float4 zv1 = *(const float4*)&sZ[r1 * 64 + k];
        const float* s0p = (const float*)&sv0;
        const float* s1p = (const float*)&sv1;
        const float* z0p = (const float*)&zv0;
        const float* z1p = (const float*)&zv1;
        #pragma unroll
        for (int kk = 0; kk < 4; kk++) {
            ulonglong2 aw = __ldg((const ulonglong2*)&w1[(k + kk) * 64 + 4 * cg]);
            ulonglong2 bw = __ldg((const ulonglong2*)&w2[(k + kk) * 64 + 4 * cg]);
            unsigned long long s0d = f2dup(s0p[kk]);
            unsigned long long s1d = f2dup(s1p[kk]);
            unsigned long long z0d = f2dup(z0p[kk]);
            unsigned long long z1d = f2dup(z1p[kk]);
            acc00 = f2fma(s0d, aw.x, acc00);
            acc00 = f2fma(z0d, bw.x, acc00);
            acc01 = f2fma(s0d, aw.y, acc01);
            acc01 = f2fma(z0d, bw.y, acc01);
            acc10 = f2fma(s1d, aw.x, acc10);
            acc10 = f2fma(z1d, bw.x, acc10);
            acc11 = f2fma(s1d, aw.y, acc11);
            acc11 = f2fma(z1d, bw.y, acc11);
        }
    }

    // epilogue
    float o[2][4];
    f2unpack(acc00, o[0][0], o[0][1]);
    f2unpack(acc01, o[0][2], o[0][3]);
    f2unpack(acc10, o[1][0], o[1][1]);
    f2unpack(acc11, o[1][2], o[1][3]);
    #pragma unroll
    for (int r = 0; r < 2; r++) {
        #pragma unroll
        for (int c = 0; c < 4; c++) {
            float v = o[r][c];
            o[r][c] = (v > 0.f) ? v : 0.01f * v;
        }
    }
    #pragma unroll
    for (int r = 0; r < 2; r++) {
        int row = row0 + r0 + r;
        if (row < N_NODES) {
            int base = row * 64 + 4 * cg;
            if (final_layer) {
                float4 ac = *(const float4*)&g_acc[base];
                float4 res;
                res.x = (ac.x + o[r][0]) * 0.25f;
                res.y = (ac.y + o[r][1]) * 0.25f;
                res.z = (ac.z + o[r][2]) * 0.25f;
                res.w = (ac.w + o[r][3]) * 0.25f;
                *(float4*)&dout[base] = res;
            } else {
                *(float4*)&dst[base] = make_float4(o[r][0], o[r][1], o[r][2], o[r][3]);
                float4 ac = *(const float4*)&g_acc[base];
                ac.x += o[r][0]; ac.y += o[r][1]; ac.z += o[r][2]; ac.w += o[r][3];
                *(float4*)&g_acc[base] = ac;
            }
        }
    }
}

// ---------------- launch -----------------------------------------------------
extern "C" void kernel_launch(void* const* d_in, const int* in_sizes, int n_in,
                              void* d_out, int out_size) {
    const float* user_emb = (const float*)d_in[0];
    const float* item_emb = (const float*)d_in[1];
    const float* w1       = (const float*)d_in[2];   // [3,64,64]
    const float* w2       = (const float*)d_in[3];   // [3,64,64]
    const float* adj_vals = (const float*)d_in[4];
    const int*   adj_rows = (const int*)d_in[5];
    const int*   adj_cols = (const int*)d_in[6];
    float* dout = (float*)d_out;

    // 3 setup launches; 4th launch (ncu -s 5 slot) = k_spmm layer 0
    k_init_hist<<<(N_NODES * EMB + 255) / 256, 256>>>(user_emb, item_emb, adj_rows);
    k_scan_lookback<<<NB_SCAN, 1024>>>();
    k_scatter<<<(NNZ + 255) / 256, 256>>>(adj_rows, adj_cols, adj_vals);

    const int SPMM_BLOCKS  = (N_NODES * 32 + 255) / 256;   // warp per row
    const int LAYER_BLOCKS = (N_NODES + TILE - 1) / TILE;  // tile per block

    for (int k = 0; k < LAYERS; k++) {
        k_spmm<<<SPMM_BLOCKS, 256>>>(k & 1);
        k_layer<<<LAYER_BLOCKS, 256>>>(w1 + k * EMB * EMB, w2 + k * EMB * EMB,
                                       dout, k & 1, k == LAYERS - 1);
    }
    (void)in_sizes; (void)n_in; (void)out_size;
}